// round 1
// baseline (speedup 1.0000x reference)
#include <cuda_runtime.h>

#define N_NODES 100000
#define N_EDGES 1000000
#define IN_CH   166
#define HID     128
#define OUTC    2

// ---------------- scratch (device globals: allocation-free rule) ----------------
__device__ float g_deg[N_NODES];
__device__ float g_inv[N_NODES];
__device__ float g_z  [(size_t)N_NODES * 2 * HID];  // z = x @ [W_l | W_r], stride 256
__device__ float g_agg[(size_t)N_NODES * HID];      // scatter accumulator (reused, first 2N for final)
__device__ float g_h  [(size_t)N_NODES * HID];      // hidden activations (reused in place)
__device__ int   g_is64;

// ---------------- utility ----------------
__global__ void zero_k(float* p, int n) {
    for (int i = blockIdx.x * blockDim.x + threadIdx.x; i < n; i += gridDim.x * blockDim.x)
        p[i] = 0.0f;
}

// Detect int64 vs int32 edge_index: if int64 (values < 1e5), every odd 32-bit word is 0.
__global__ void detect_k(const unsigned* w) {
    int nz = 0;
    for (int i = 0; i < 256; i++) nz += (w[2 * i + 1] != 0u);
    g_is64 = (nz == 0) ? 1 : 0;
}

__device__ __forceinline__ void load_edge(const void* ei, int e, int is64, int& src, int& dst) {
    if (is64) {
        const long long* p = (const long long*)ei;
        src = (int)p[e];
        dst = (int)p[N_EDGES + e];
    } else {
        const int* p = (const int*)ei;
        src = p[e];
        dst = p[N_EDGES + e];
    }
}

// ---------------- degree ----------------
__global__ void deg_k(const void* ei) {
    int e = blockIdx.x * blockDim.x + threadIdx.x;
    if (e >= N_EDGES) return;
    int is64 = g_is64, src, dst;
    load_edge(ei, e, is64, src, dst);
    atomicAdd(&g_deg[dst], 1.0f);
}

__global__ void inv_k() {
    int i = blockIdx.x * blockDim.x + threadIdx.x;
    if (i < N_NODES) g_inv[i] = 1.0f / fmaxf(g_deg[i], 1.0f);
}

// ---------------- fused dual GEMM: Z[:, half] = A @ W  (W = W_l or W_r by blockIdx.y) ----
// A: [N, K] row-major, W: [K, HID] row-major, Z: [N, 2*HID].
// Tile: BM=128 rows x BN=128 cols, BK=16. 256 threads, 8x8 per thread.
__global__ __launch_bounds__(256) void gemm_dual(const float* __restrict__ A, int K,
                                                 const float* __restrict__ Wl,
                                                 const float* __restrict__ Wr,
                                                 float* __restrict__ Z) {
    const float* __restrict__ W = blockIdx.y ? Wr : Wl;
    const int row0 = blockIdx.x * 128;
    const int tx = threadIdx.x & 15;
    const int ty = threadIdx.x >> 4;

    __shared__ float As[128][17];
    __shared__ float Bs[16][128];

    float acc[8][8];
#pragma unroll
    for (int i = 0; i < 8; i++)
#pragma unroll
        for (int j = 0; j < 8; j++) acc[i][j] = 0.0f;

    for (int k0 = 0; k0 < K; k0 += 16) {
        // load A tile: 128x16 = 2048 elems / 256 threads = 8 each
#pragma unroll
        for (int i = 0; i < 8; i++) {
            int l = threadIdx.x + i * 256;
            int r = l >> 4, c = l & 15;
            int row = row0 + r, k = k0 + c;
            As[r][c] = (row < N_NODES && k < K) ? A[(size_t)row * K + k] : 0.0f;
        }
        // load B tile: 16x128 = 2048 elems / 256 threads = 8 each (fully coalesced)
#pragma unroll
        for (int i = 0; i < 8; i++) {
            int l = threadIdx.x + i * 256;
            int r = l >> 7, c = l & 127;
            int k = k0 + r;
            Bs[r][c] = (k < K) ? W[(size_t)k * HID + c] : 0.0f;
        }
        __syncthreads();

#pragma unroll
        for (int kk = 0; kk < 16; kk++) {
            float a[8], b[8];
#pragma unroll
            for (int i = 0; i < 8; i++) a[i] = As[ty + 16 * i][kk];
#pragma unroll
            for (int j = 0; j < 8; j++) b[j] = Bs[kk][tx + 16 * j];
#pragma unroll
            for (int i = 0; i < 8; i++)
#pragma unroll
                for (int j = 0; j < 8; j++) acc[i][j] += a[i] * b[j];
        }
        __syncthreads();
    }

    const int colBase = blockIdx.y * HID;
#pragma unroll
    for (int i = 0; i < 8; i++) {
        int row = row0 + ty + 16 * i;
        if (row >= N_NODES) continue;
#pragma unroll
        for (int j = 0; j < 8; j++)
            Z[(size_t)row * (2 * HID) + colBase + tx + 16 * j] = acc[i][j];
    }
}

// ---------------- scatter: agg[dst] += Z[src][0:HID]  (warp per edge) ----------------
__global__ void scatter_k(const void* ei, const float* __restrict__ Z) {
    int gt = blockIdx.x * blockDim.x + threadIdx.x;
    int e = gt >> 5;
    if (e >= N_EDGES) return;
    int lane = gt & 31;
    int is64 = g_is64, src, dst;
    load_edge(ei, e, is64, src, dst);
    const float* zr = Z + (size_t)src * (2 * HID);
    float* ar = g_agg + (size_t)dst * HID;
#pragma unroll
    for (int c = lane; c < HID; c += 32)
        atomicAdd(ar + c, zr[c]);
}

// ---------------- combine: h = relu(agg * inv_deg + z_r + b) ----------------
__global__ void combine_relu_k(const float* __restrict__ Z, const float* __restrict__ b,
                               float* __restrict__ Hout) {
    int idx = blockIdx.x * blockDim.x + threadIdx.x;
    if (idx >= N_NODES * HID) return;
    int i = idx >> 7, c = idx & 127;
    float v = g_agg[idx] * g_inv[i] + Z[(size_t)i * (2 * HID) + HID + c] + b[c];
    Hout[idx] = fmaxf(v, 0.0f);
}

// ---------------- final layer (HID -> 2): Zf[row] = [h@Wl2(2), h@Wr2(2)] ----------------
__global__ void final_gemm_k(const float* __restrict__ Hin,
                             const float* __restrict__ Wl,
                             const float* __restrict__ Wr,
                             float* __restrict__ Zf) {
    int row = blockIdx.x;
    int t = threadIdx.x;  // 128
    float h = Hin[(size_t)row * HID + t];
    float a0 = h * Wl[2 * t + 0];
    float a1 = h * Wl[2 * t + 1];
    float a2 = h * Wr[2 * t + 0];
    float a3 = h * Wr[2 * t + 1];
#pragma unroll
    for (int o = 16; o > 0; o >>= 1) {
        a0 += __shfl_down_sync(0xFFFFFFFFu, a0, o);
        a1 += __shfl_down_sync(0xFFFFFFFFu, a1, o);
        a2 += __shfl_down_sync(0xFFFFFFFFu, a2, o);
        a3 += __shfl_down_sync(0xFFFFFFFFu, a3, o);
    }
    __shared__ float s[4][4];
    int w = t >> 5;
    if ((t & 31) == 0) { s[w][0] = a0; s[w][1] = a1; s[w][2] = a2; s[w][3] = a3; }
    __syncthreads();
    if (t < 4)
        Zf[(size_t)row * 4 + t] = s[0][t] + s[1][t] + s[2][t] + s[3][t];
}

// ---------------- final scatter (2 channels, thread per edge) ----------------
__global__ void scatter2_k(const void* ei, const float* __restrict__ Zf) {
    int e = blockIdx.x * blockDim.x + threadIdx.x;
    if (e >= N_EDGES) return;
    int is64 = g_is64, src, dst;
    load_edge(ei, e, is64, src, dst);
    float z0 = Zf[(size_t)src * 4 + 0];
    float z1 = Zf[(size_t)src * 4 + 1];
    atomicAdd(&g_agg[2 * dst + 0], z0);
    atomicAdd(&g_agg[2 * dst + 1], z1);
}

// ---------------- final combine (no relu) ----------------
__global__ void combine_final_k(const float* __restrict__ Zf, const float* __restrict__ b,
                                float* __restrict__ out) {
    int idx = blockIdx.x * blockDim.x + threadIdx.x;
    if (idx >= N_NODES * OUTC) return;
    int i = idx >> 1, c = idx & 1;
    out[idx] = g_agg[idx] * g_inv[i] + Zf[(size_t)i * 4 + 2 + c] + b[c];
}

// ---------------- launcher ----------------
extern "C" void kernel_launch(void* const* d_in, const int* in_sizes, int n_in,
                              void* d_out, int out_size) {
    const float* x   = (const float*)d_in[0];
    const void*  ei  = d_in[1];
    const float* Wl0 = (const float*)d_in[2];
    const float* b0  = (const float*)d_in[3];
    const float* Wr0 = (const float*)d_in[4];
    const float* Wl1 = (const float*)d_in[5];
    const float* b1  = (const float*)d_in[6];
    const float* Wr1 = (const float*)d_in[7];
    const float* Wl2 = (const float*)d_in[8];
    const float* b2  = (const float*)d_in[9];
    const float* Wr2 = (const float*)d_in[10];
    float* out = (float*)d_out;

    float *deg_p, *z_p, *agg_p, *h_p;
    cudaGetSymbolAddress((void**)&deg_p, g_deg);
    cudaGetSymbolAddress((void**)&z_p,   g_z);
    cudaGetSymbolAddress((void**)&agg_p, g_agg);
    cudaGetSymbolAddress((void**)&h_p,   g_h);

    const int gemm_gx = (N_NODES + 127) / 128;  // 782

    detect_k<<<1, 1>>>((const unsigned*)ei);

    // degrees (shared by all layers)
    zero_k<<<512, 256>>>(deg_p, N_NODES);
    deg_k<<<(N_EDGES + 255) / 256, 256>>>(ei);
    inv_k<<<(N_NODES + 255) / 256, 256>>>();

    // ---- layer 0: z = x @ [Wl0|Wr0]; agg = scatter(z_l); h = relu(mean + z_r + b0)
    gemm_dual<<<dim3(gemm_gx, 2), 256>>>(x, IN_CH, Wl0, Wr0, z_p);
    zero_k<<<4096, 256>>>(agg_p, N_NODES * HID);
    scatter_k<<<(N_EDGES * 32 + 255) / 256, 256>>>(ei, z_p);
    combine_relu_k<<<(N_NODES * HID + 255) / 256, 256>>>(z_p, b0, h_p);

    // ---- layer 1
    gemm_dual<<<dim3(gemm_gx, 2), 256>>>(h_p, HID, Wl1, Wr1, z_p);
    zero_k<<<4096, 256>>>(agg_p, N_NODES * HID);
    scatter_k<<<(N_EDGES * 32 + 255) / 256, 256>>>(ei, z_p);
    combine_relu_k<<<(N_NODES * HID + 255) / 256, 256>>>(z_p, b1, h_p);

    // ---- layer 2 (output dim 2): transform first, scatter only 2 channels
    final_gemm_k<<<N_NODES, HID>>>(h_p, Wl2, Wr2, z_p);   // z_p reused as Zf [N,4]
    zero_k<<<512, 256>>>(agg_p, N_NODES * OUTC);
    scatter2_k<<<(N_EDGES + 255) / 256, 256>>>(ei, z_p);
    combine_final_k<<<(N_NODES * OUTC + 255) / 256, 256>>>(z_p, b2, out);
}

// round 2
// speedup vs baseline: 1.0103x; 1.0103x over previous
#include <cuda_runtime.h>

#define N_NODES 100000
#define N_EDGES 1000000
#define IN_CH   166
#define HID     128
#define OUTC    2

// ---------------- scratch (device globals: allocation-free rule) ----------------
__device__ float g_deg[N_NODES];
__device__ float g_inv[N_NODES];
__device__ float g_z  [(size_t)N_NODES * 2 * HID];  // z = x @ [W_l | W_r], stride 256
__device__ float g_agg[(size_t)N_NODES * HID];      // scatter accumulator (reused, first 2N for final)
__device__ float g_h  [(size_t)N_NODES * HID];      // hidden activations (reused in place)
__device__ int   g_is64;

// ---------------- utility ----------------
__global__ void zero_k(float* p, int n) {
    for (int i = blockIdx.x * blockDim.x + threadIdx.x; i < n; i += gridDim.x * blockDim.x)
        p[i] = 0.0f;
}

// Detect int64 vs int32 edge_index: if int64 (values < 1e5), every odd 32-bit word is 0.
__global__ void detect_k(const unsigned* w) {
    int nz = 0;
    for (int i = 0; i < 256; i++) nz += (w[2 * i + 1] != 0u);
    g_is64 = (nz == 0) ? 1 : 0;
}

__device__ __forceinline__ void load_edge(const void* ei, int e, int is64, int& src, int& dst) {
    if (is64) {
        const long long* p = (const long long*)ei;
        src = (int)p[e];
        dst = (int)p[N_EDGES + e];
    } else {
        const int* p = (const int*)ei;
        src = p[e];
        dst = p[N_EDGES + e];
    }
}

// ---------------- degree ----------------
__global__ void deg_k(const void* ei) {
    int e = blockIdx.x * blockDim.x + threadIdx.x;
    if (e >= N_EDGES) return;
    int is64 = g_is64, src, dst;
    load_edge(ei, e, is64, src, dst);
    atomicAdd(&g_deg[dst], 1.0f);
}

__global__ void inv_k() {
    int i = blockIdx.x * blockDim.x + threadIdx.x;
    if (i < N_NODES) g_inv[i] = 1.0f / fmaxf(g_deg[i], 1.0f);
}

// ---------------- fused dual GEMM: Z[:, half] = A @ W  (W = W_l or W_r by blockIdx.y) ----
// A: [N, K] row-major, W: [K, HID] row-major, Z: [N, 2*HID].
// Tile: BM=128 rows x BN=128 cols, BK=16. 256 threads, 8x8 per thread.
__global__ __launch_bounds__(256) void gemm_dual(const float* __restrict__ A, int K,
                                                 const float* __restrict__ Wl,
                                                 const float* __restrict__ Wr,
                                                 float* __restrict__ Z) {
    const float* __restrict__ W = blockIdx.y ? Wr : Wl;
    const int row0 = blockIdx.x * 128;
    const int tx = threadIdx.x & 15;
    const int ty = threadIdx.x >> 4;

    __shared__ float As[128][17];
    __shared__ float Bs[16][128];

    float acc[8][8];
#pragma unroll
    for (int i = 0; i < 8; i++)
#pragma unroll
        for (int j = 0; j < 8; j++) acc[i][j] = 0.0f;

    for (int k0 = 0; k0 < K; k0 += 16) {
        // load A tile: 128x16 = 2048 elems / 256 threads = 8 each
#pragma unroll
        for (int i = 0; i < 8; i++) {
            int l = threadIdx.x + i * 256;
            int r = l >> 4, c = l & 15;
            int row = row0 + r, k = k0 + c;
            As[r][c] = (row < N_NODES && k < K) ? A[(size_t)row * K + k] : 0.0f;
        }
        // load B tile: 16x128 = 2048 elems / 256 threads = 8 each (fully coalesced)
#pragma unroll
        for (int i = 0; i < 8; i++) {
            int l = threadIdx.x + i * 256;
            int r = l >> 7, c = l & 127;
            int k = k0 + r;
            Bs[r][c] = (k < K) ? W[(size_t)k * HID + c] : 0.0f;
        }
        __syncthreads();

#pragma unroll
        for (int kk = 0; kk < 16; kk++) {
            float a[8], b[8];
#pragma unroll
            for (int i = 0; i < 8; i++) a[i] = As[ty + 16 * i][kk];
#pragma unroll
            for (int j = 0; j < 8; j++) b[j] = Bs[kk][tx + 16 * j];
#pragma unroll
            for (int i = 0; i < 8; i++)
#pragma unroll
                for (int j = 0; j < 8; j++) acc[i][j] += a[i] * b[j];
        }
        __syncthreads();
    }

    const int colBase = blockIdx.y * HID;
#pragma unroll
    for (int i = 0; i < 8; i++) {
        int row = row0 + ty + 16 * i;
        if (row >= N_NODES) continue;
#pragma unroll
        for (int j = 0; j < 8; j++)
            Z[(size_t)row * (2 * HID) + colBase + tx + 16 * j] = acc[i][j];
    }
}

// ---------------- scatter: agg[dst] += Z[src][0:HID]  (warp per edge) ----------------
__global__ void scatter_k(const void* ei, const float* __restrict__ Z) {
    int gt = blockIdx.x * blockDim.x + threadIdx.x;
    int e = gt >> 5;
    if (e >= N_EDGES) return;
    int lane = gt & 31;
    int is64 = g_is64, src, dst;
    load_edge(ei, e, is64, src, dst);
    const float* zr = Z + (size_t)src * (2 * HID);
    float* ar = g_agg + (size_t)dst * HID;
#pragma unroll
    for (int c = lane; c < HID; c += 32)
        atomicAdd(ar + c, zr[c]);
}

// ---------------- combine: h = relu(agg * inv_deg + z_r + b) ----------------
__global__ void combine_relu_k(const float* __restrict__ Z, const float* __restrict__ b,
                               float* __restrict__ Hout) {
    int idx = blockIdx.x * blockDim.x + threadIdx.x;
    if (idx >= N_NODES * HID) return;
    int i = idx >> 7, c = idx & 127;
    float v = g_agg[idx] * g_inv[i] + Z[(size_t)i * (2 * HID) + HID + c] + b[c];
    Hout[idx] = fmaxf(v, 0.0f);
}

// ---------------- final layer (HID -> 2): Zf[row] = [h@Wl2(2), h@Wr2(2)] ----------------
__global__ void final_gemm_k(const float* __restrict__ Hin,
                             const float* __restrict__ Wl,
                             const float* __restrict__ Wr,
                             float* __restrict__ Zf) {
    int row = blockIdx.x;
    int t = threadIdx.x;  // 128
    float h = Hin[(size_t)row * HID + t];
    float a0 = h * Wl[2 * t + 0];
    float a1 = h * Wl[2 * t + 1];
    float a2 = h * Wr[2 * t + 0];
    float a3 = h * Wr[2 * t + 1];
#pragma unroll
    for (int o = 16; o > 0; o >>= 1) {
        a0 += __shfl_down_sync(0xFFFFFFFFu, a0, o);
        a1 += __shfl_down_sync(0xFFFFFFFFu, a1, o);
        a2 += __shfl_down_sync(0xFFFFFFFFu, a2, o);
        a3 += __shfl_down_sync(0xFFFFFFFFu, a3, o);
    }
    __shared__ float s[4][4];
    int w = t >> 5;
    if ((t & 31) == 0) { s[w][0] = a0; s[w][1] = a1; s[w][2] = a2; s[w][3] = a3; }
    __syncthreads();
    if (t < 4)
        Zf[(size_t)row * 4 + t] = s[0][t] + s[1][t] + s[2][t] + s[3][t];
}

// ---------------- final scatter (2 channels, thread per edge) ----------------
__global__ void scatter2_k(const void* ei, const float* __restrict__ Zf) {
    int e = blockIdx.x * blockDim.x + threadIdx.x;
    if (e >= N_EDGES) return;
    int is64 = g_is64, src, dst;
    load_edge(ei, e, is64, src, dst);
    float z0 = Zf[(size_t)src * 4 + 0];
    float z1 = Zf[(size_t)src * 4 + 1];
    atomicAdd(&g_agg[2 * dst + 0], z0);
    atomicAdd(&g_agg[2 * dst + 1], z1);
}

// ---------------- final combine (no relu) ----------------
__global__ void combine_final_k(const float* __restrict__ Zf, const float* __restrict__ b,
                                float* __restrict__ out) {
    int idx = blockIdx.x * blockDim.x + threadIdx.x;
    if (idx >= N_NODES * OUTC) return;
    int i = idx >> 1, c = idx & 1;
    out[idx] = g_agg[idx] * g_inv[i] + Zf[(size_t)i * 4 + 2 + c] + b[c];
}

// ---------------- launcher ----------------
extern "C" void kernel_launch(void* const* d_in, const int* in_sizes, int n_in,
                              void* d_out, int out_size) {
    const float* x   = (const float*)d_in[0];
    const void*  ei  = d_in[1];
    const float* Wl0 = (const float*)d_in[2];
    const float* b0  = (const float*)d_in[3];
    const float* Wr0 = (const float*)d_in[4];
    const float* Wl1 = (const float*)d_in[5];
    const float* b1  = (const float*)d_in[6];
    const float* Wr1 = (const float*)d_in[7];
    const float* Wl2 = (const float*)d_in[8];
    const float* b2  = (const float*)d_in[9];
    const float* Wr2 = (const float*)d_in[10];
    float* out = (float*)d_out;

    float *deg_p, *z_p, *agg_p, *h_p;
    cudaGetSymbolAddress((void**)&deg_p, g_deg);
    cudaGetSymbolAddress((void**)&z_p,   g_z);
    cudaGetSymbolAddress((void**)&agg_p, g_agg);
    cudaGetSymbolAddress((void**)&h_p,   g_h);

    const int gemm_gx = (N_NODES + 127) / 128;  // 782

    detect_k<<<1, 1>>>((const unsigned*)ei);

    // degrees (shared by all layers)
    zero_k<<<512, 256>>>(deg_p, N_NODES);
    deg_k<<<(N_EDGES + 255) / 256, 256>>>(ei);
    inv_k<<<(N_NODES + 255) / 256, 256>>>();

    // ---- layer 0: z = x @ [Wl0|Wr0]; agg = scatter(z_l); h = relu(mean + z_r + b0)
    gemm_dual<<<dim3(gemm_gx, 2), 256>>>(x, IN_CH, Wl0, Wr0, z_p);
    zero_k<<<4096, 256>>>(agg_p, N_NODES * HID);
    scatter_k<<<(N_EDGES * 32 + 255) / 256, 256>>>(ei, z_p);
    combine_relu_k<<<(N_NODES * HID + 255) / 256, 256>>>(z_p, b0, h_p);

    // ---- layer 1
    gemm_dual<<<dim3(gemm_gx, 2), 256>>>(h_p, HID, Wl1, Wr1, z_p);
    zero_k<<<4096, 256>>>(agg_p, N_NODES * HID);
    scatter_k<<<(N_EDGES * 32 + 255) / 256, 256>>>(ei, z_p);
    combine_relu_k<<<(N_NODES * HID + 255) / 256, 256>>>(z_p, b1, h_p);

    // ---- layer 2 (output dim 2): transform first, scatter only 2 channels
    final_gemm_k<<<N_NODES, HID>>>(h_p, Wl2, Wr2, z_p);   // z_p reused as Zf [N,4]
    zero_k<<<512, 256>>>(agg_p, N_NODES * OUTC);
    scatter2_k<<<(N_EDGES + 255) / 256, 256>>>(ei, z_p);
    combine_final_k<<<(N_NODES * OUTC + 255) / 256, 256>>>(z_p, b2, out);
}

// round 4
// speedup vs baseline: 2.1658x; 2.1437x over previous
#include <cuda_runtime.h>
#include <cuda_bf16.h>
#include <cstdint>

#define N_NODES 100000
#define N_EDGES 1000000
#define IN_CH   166
#define HID     128
#define KCAT0   512
#define KCAT1   384

#define BM 128
#define BN 128
#define BK 32
#define PADB 80   // bytes per smem row (32 bf16 = 64B data + 16B pad)

// ---------------- device scratch ----------------
__device__ int   g_deg[N_NODES];
__device__ float g_inv[N_NODES];
__device__ int   g_rowptr[N_NODES + 1];
__device__ int   g_cursor[N_NODES];
__device__ int   g_col[N_EDGES];
__device__ int   g_bsum[128];
__device__ int   g_boff[128];
__device__ __align__(16) __nv_bfloat16 g_acat[(size_t)N_NODES * KCAT0];
__device__ __align__(16) __nv_bfloat16 g_bcat[(size_t)256 * KCAT0];
__device__ float g_z[(size_t)N_NODES * 256];
__device__ float g_h[(size_t)N_NODES * HID];
__device__ int   g_is64;

// ---------------- PTX helpers ----------------
__device__ __forceinline__ uint32_t smem_u32(const void* p) {
    uint32_t a;
    asm("{ .reg .u64 t; cvta.to.shared.u64 t, %1; cvt.u32.u64 %0, t; }" : "=r"(a) : "l"(p));
    return a;
}
__device__ __forceinline__ void cp16(uint32_t dst, const void* src, int sz) {
    asm volatile("cp.async.cg.shared.global [%0], [%1], 16, %2;\n" :: "r"(dst), "l"(src), "r"(sz));
}
#define CP_COMMIT() asm volatile("cp.async.commit_group;\n" ::: "memory")
#define CP_WAIT1()  asm volatile("cp.async.wait_group 1;\n" ::: "memory")
#define CP_WAIT0()  asm volatile("cp.async.wait_group 0;\n" ::: "memory")

__device__ __forceinline__ void ldsm4(uint32_t* r, uint32_t addr) {
    asm volatile("ldmatrix.sync.aligned.m8n8.x4.shared.b16 {%0,%1,%2,%3}, [%4];"
        : "=r"(r[0]), "=r"(r[1]), "=r"(r[2]), "=r"(r[3]) : "r"(addr));
}
__device__ __forceinline__ void mma16816(float* c, const uint32_t* a, const uint32_t* b) {
    asm volatile("mma.sync.aligned.m16n8k16.row.col.f32.bf16.bf16.f32 "
        "{%0,%1,%2,%3}, {%4,%5,%6,%7}, {%8,%9}, {%0,%1,%2,%3};"
        : "+f"(c[0]), "+f"(c[1]), "+f"(c[2]), "+f"(c[3])
        : "r"(a[0]), "r"(a[1]), "r"(a[2]), "r"(a[3]), "r"(b[0]), "r"(b[1]));
}

// ---------------- edge utils / CSR build ----------------
__global__ void detect_k(const unsigned* w) {
    __shared__ int s;
    if (threadIdx.x == 0) s = 0;
    __syncthreads();
    if (w[2 * threadIdx.x + 1] != 0u) atomicAdd(&s, 1);
    __syncthreads();
    if (threadIdx.x == 0) g_is64 = (s == 0) ? 1 : 0;
}

__device__ __forceinline__ void load_edge(const void* ei, int e, int is64, int& src, int& dst) {
    if (is64) {
        const long long* p = (const long long*)ei;
        src = (int)p[e]; dst = (int)p[N_EDGES + e];
    } else {
        const int* p = (const int*)ei;
        src = p[e]; dst = p[N_EDGES + e];
    }
}

__global__ void zeroi_k() {
    int i = blockIdx.x * blockDim.x + threadIdx.x;
    if (i < N_NODES) g_deg[i] = 0;
}
__global__ void deg_k(const void* ei) {
    int e = blockIdx.x * blockDim.x + threadIdx.x;
    if (e >= N_EDGES) return;
    int is64 = g_is64, src, dst;
    load_edge(ei, e, is64, src, dst);
    atomicAdd(&g_deg[dst], 1);
}
__global__ void scan1_k() {
    __shared__ int s[1024];
    int g = blockIdx.x * 1024 + threadIdx.x;
    int v = (g < N_NODES) ? g_deg[g] : 0;
    s[threadIdx.x] = v;
    __syncthreads();
    for (int o = 1; o < 1024; o <<= 1) {
        int t = (threadIdx.x >= o) ? s[threadIdx.x - o] : 0;
        __syncthreads();
        s[threadIdx.x] += t;
        __syncthreads();
    }
    if (g < N_NODES) g_rowptr[g] = s[threadIdx.x] - v;
    if (threadIdx.x == 1023) g_bsum[blockIdx.x] = s[1023];
}
__global__ void scan2_k(int nb) {
    __shared__ int s[128];
    int t = threadIdx.x;
    int v = (t < nb) ? g_bsum[t] : 0;
    s[t] = v;
    __syncthreads();
    for (int o = 1; o < 128; o <<= 1) {
        int a = (t >= o) ? s[t - o] : 0;
        __syncthreads();
        s[t] += a;
        __syncthreads();
    }
    if (t < nb) g_boff[t] = s[t] - v;
}
__global__ void scan3_k() {
    int g = blockIdx.x * 1024 + threadIdx.x;
    if (g >= N_NODES) return;
    int rp = g_rowptr[g] + g_boff[blockIdx.x];
    g_rowptr[g] = rp;
    g_cursor[g] = rp;
    g_inv[g] = 1.0f / fmaxf((float)g_deg[g], 1.0f);
    if (g == 0) g_rowptr[N_NODES] = N_EDGES;
}
__global__ void place_k(const void* ei) {
    int e = blockIdx.x * blockDim.x + threadIdx.x;
    if (e >= N_EDGES) return;
    int is64 = g_is64, src, dst;
    load_edge(ei, e, is64, src, dst);
    g_col[atomicAdd(&g_cursor[dst], 1)] = src;
}

// ---------------- split-bf16 operand builders ----------------
__global__ void build_acat(const float* __restrict__ X, int K, int Kcat) {
    int w = (blockIdx.x * blockDim.x + threadIdx.x) >> 5;
    if (w >= N_NODES) return;
    int lane = threadIdx.x & 31;
    const float* xr = X + (size_t)w * K;
    __nv_bfloat16* row = g_acat + (size_t)w * Kcat;
    for (int k = lane; k < K; k += 32) {
        float v = xr[k];
        __nv_bfloat16 hi = __float2bfloat16(v);
        row[k] = hi;
        row[K + k] = __float2bfloat16(v - __bfloat162float(hi));
        row[2 * K + k] = hi;
    }
    for (int p = 3 * K + lane; p < Kcat; p += 32) row[p] = __float2bfloat16(0.0f);
}
__global__ void build_bcat(const float* __restrict__ Wl, const float* __restrict__ Wr,
                           int K, int Kcat) {
    int n = blockIdx.x;  // 0..255
    const float* W = (n < 128) ? Wl : Wr;
    int nn = n & 127;
    __nv_bfloat16* row = g_bcat + (size_t)n * Kcat;
    for (int k = threadIdx.x; k < Kcat; k += blockDim.x) {
        __nv_bfloat16 o = __float2bfloat16(0.0f);
        if (k < 2 * K) {
            int kk = (k < K) ? k : (k - K);
            o = __float2bfloat16(W[(size_t)kk * HID + nn]);
        } else if (k < 3 * K) {
            float v = W[(size_t)(k - 2 * K) * HID + nn];
            __nv_bfloat16 hi = __float2bfloat16(v);
            o = __float2bfloat16(v - __bfloat162float(hi));
        }
        row[k] = o;
    }
}

// ---------------- HMMA GEMM: Z[N,256] = A_cat[N,Kcat] @ B_cat[256,Kcat]^T -------------
// BM=128, BN=128 (gridDim.y=2 covers 256 cols), BK=32, 256 thr, warps 4(m) x 2(n).
__global__ __launch_bounds__(256) void gemm_mma(const __nv_bfloat16* __restrict__ A, int Kcat,
                                                const __nv_bfloat16* __restrict__ B,
                                                float* __restrict__ Z) {
    __shared__ __align__(16) char As[2][BM * PADB];
    __shared__ __align__(16) char Bs[2][BN * PADB];
    const int tid = threadIdx.x, lane = tid & 31, wid = tid >> 5;
    const int wm = wid & 3, wn = wid >> 2;
    const int m0 = blockIdx.x * BM, n0 = blockIdx.y * BN;
    const char* Ab = (const char*)A;
    const char* Bb = (const char*)B;
    const size_t rowb = (size_t)Kcat * 2;
    const uint32_t uas = smem_u32(As), ubs = smem_u32(Bs);

    float acc[2][8][4];
#pragma unroll
    for (int i = 0; i < 2; i++)
#pragma unroll
        for (int j = 0; j < 8; j++)
#pragma unroll
            for (int k = 0; k < 4; k++) acc[i][j][k] = 0.0f;

    auto load_stage = [&](int kt, int s) {
        const int k0b = kt * BK * 2;
        const uint32_t a_s = uas + s * (BM * PADB);
        const uint32_t b_s = ubs + s * (BN * PADB);
#pragma unroll
        for (int i = 0; i < 2; i++) {
            int c = tid + (i << 8);
            int r = c >> 2, o = (c & 3) << 4;
            int row = m0 + r;
            int sz = (row < N_NODES) ? 16 : 0;
            row = min(row, N_NODES - 1);
            cp16(a_s + r * PADB + o, Ab + (size_t)row * rowb + k0b + o, sz);
        }
#pragma unroll
        for (int i = 0; i < 2; i++) {
            int c = tid + (i << 8);
            int r = c >> 2, o = (c & 3) << 4;
            cp16(b_s + r * PADB + o, Bb + (size_t)(n0 + r) * rowb + k0b + o, 16);
        }
        CP_COMMIT();
    };

    const int T = Kcat / BK;
    load_stage(0, 0);

    for (int t = 0; t < T; t++) {
        const int s = t & 1;
        if (t + 1 < T) { load_stage(t + 1, s ^ 1); CP_WAIT1(); }
        else           { CP_WAIT0(); }
        __syncthreads();

        const uint32_t a_s = uas + s * (BM * PADB);
        const uint32_t b_s = ubs + s * (BN * PADB);
#pragma unroll
        for (int kk = 0; kk < 2; kk++) {
            const int kb = kk * 32;  // byte offset of this k16 within the row
            uint32_t af[2][4];
#pragma unroll
            for (int mt = 0; mt < 2; mt++) {
                int r = wm * 32 + mt * 16 + (lane & 15);
                ldsm4(af[mt], a_s + r * PADB + kb + ((lane >> 4) << 4));
            }
            uint32_t bf[4][4];
#pragma unroll
            for (int np = 0; np < 4; np++) {
                int r = wn * 64 + np * 16 + (lane & 7) + ((lane >> 4) << 3);
                ldsm4(bf[np], b_s + r * PADB + kb + (((lane >> 3) & 1) << 4));
            }
#pragma unroll
            for (int mt = 0; mt < 2; mt++)
#pragma unroll
                for (int nt = 0; nt < 8; nt++)
                    mma16816(acc[mt][nt], af[mt], &bf[nt >> 1][(nt & 1) * 2]);
        }
        __syncthreads();
    }

    // epilogue
#pragma unroll
    for (int mt = 0; mt < 2; mt++) {
        int r0 = m0 + wm * 32 + mt * 16 + (lane >> 2);
#pragma unroll
        for (int half = 0; half < 2; half++) {
            int row = r0 + half * 8;
            if (row < N_NODES) {
#pragma unroll
                for (int nt = 0; nt < 8; nt++) {
                    int col = n0 + wn * 64 + nt * 8 + ((lane & 3) << 1);
                    *(float2*)(Z + (size_t)row * 256 + col) =
                        make_float2(acc[mt][nt][half * 2], acc[mt][nt][half * 2 + 1]);
                }
            }
        }
    }
}

// ---------------- CSR gather + fused combine: h = relu(mean(z_l) + z_r + b) ----------
__global__ void gather_combine(const float* __restrict__ Z, const float* __restrict__ bias,
                               float* __restrict__ H) {
    int w = (blockIdx.x * blockDim.x + threadIdx.x) >> 5;
    if (w >= N_NODES) return;
    int lane = threadIdx.x & 31;
    int beg = g_rowptr[w], end = g_rowptr[w + 1];
    float4 acc = make_float4(0.f, 0.f, 0.f, 0.f);
    int j = beg;
    for (; j + 1 < end; j += 2) {
        int c0 = g_col[j], c1 = g_col[j + 1];
        float4 v0 = ((const float4*)(Z + (size_t)c0 * 256))[lane];
        float4 v1 = ((const float4*)(Z + (size_t)c1 * 256))[lane];
        acc.x += v0.x + v1.x; acc.y += v0.y + v1.y;
        acc.z += v0.z + v1.z; acc.w += v0.w + v1.w;
    }
    if (j < end) {
        float4 v = ((const float4*)(Z + (size_t)g_col[j] * 256))[lane];
        acc.x += v.x; acc.y += v.y; acc.z += v.z; acc.w += v.w;
    }
    float inv = g_inv[w];
    float4 zr = ((const float4*)(Z + (size_t)w * 256 + 128))[lane];
    float4 bv = ((const float4*)bias)[lane];
    float4 o;
    o.x = fmaxf(acc.x * inv + zr.x + bv.x, 0.f);
    o.y = fmaxf(acc.y * inv + zr.y + bv.y, 0.f);
    o.z = fmaxf(acc.z * inv + zr.z + bv.z, 0.f);
    o.w = fmaxf(acc.w * inv + zr.w + bv.w, 0.f);
    ((float4*)(H + (size_t)w * HID))[lane] = o;
}

// ---------------- final layer (HID -> 2) ----------------
__global__ void final_gemm_k(const float* __restrict__ Hin, const float* __restrict__ Wl,
                             const float* __restrict__ Wr, float* __restrict__ Zf) {
    int row = blockIdx.x;
    int t = threadIdx.x;
    float h = Hin[(size_t)row * HID + t];
    float a0 = h * Wl[2 * t], a1 = h * Wl[2 * t + 1];
    float a2 = h * Wr[2 * t], a3 = h * Wr[2 * t + 1];
#pragma unroll
    for (int o = 16; o > 0; o >>= 1) {
        a0 += __shfl_down_sync(0xFFFFFFFFu, a0, o);
        a1 += __shfl_down_sync(0xFFFFFFFFu, a1, o);
        a2 += __shfl_down_sync(0xFFFFFFFFu, a2, o);
        a3 += __shfl_down_sync(0xFFFFFFFFu, a3, o);
    }
    __shared__ float s[4][4];
    int w = t >> 5;
    if ((t & 31) == 0) { s[w][0] = a0; s[w][1] = a1; s[w][2] = a2; s[w][3] = a3; }
    __syncthreads();
    if (t < 4) Zf[(size_t)row * 4 + t] = s[0][t] + s[1][t] + s[2][t] + s[3][t];
}

__global__ void gather2_k(const float* __restrict__ Zf, const float* __restrict__ b2,
                          float* __restrict__ out) {
    int i = blockIdx.x * blockDim.x + threadIdx.x;
    if (i >= N_NODES) return;
    int beg = g_rowptr[i], end = g_rowptr[i + 1];
    float a0 = 0.f, a1 = 0.f;
    for (int j = beg; j < end; j++) {
        const float2 v = ((const float2*)Zf)[g_col[j] * 2];
        a0 += v.x; a1 += v.y;
    }
    float inv = g_inv[i];
    out[2 * i]     = a0 * inv + Zf[(size_t)i * 4 + 2] + b2[0];
    out[2 * i + 1] = a1 * inv + Zf[(size_t)i * 4 + 3] + b2[1];
}

// ---------------- launcher ----------------
extern "C" void kernel_launch(void* const* d_in, const int* in_sizes, int n_in,
                              void* d_out, int out_size) {
    const float* x   = (const float*)d_in[0];
    const void*  ei  = d_in[1];
    const float* Wl0 = (const float*)d_in[2];
    const float* b0  = (const float*)d_in[3];
    const float* Wr0 = (const float*)d_in[4];
    const float* Wl1 = (const float*)d_in[5];
    const float* b1  = (const float*)d_in[6];
    const float* Wr1 = (const float*)d_in[7];
    const float* Wl2 = (const float*)d_in[8];
    const float* b2  = (const float*)d_in[9];
    const float* Wr2 = (const float*)d_in[10];
    float* out = (float*)d_out;

    __nv_bfloat16 *ac_p, *bc_p;
    float *z_p, *h_p;
    cudaGetSymbolAddress((void**)&ac_p, g_acat);
    cudaGetSymbolAddress((void**)&bc_p, g_bcat);
    cudaGetSymbolAddress((void**)&z_p, g_z);
    cudaGetSymbolAddress((void**)&h_p, g_h);

    const int gx = (N_NODES + 127) / 128;          // 782
    const int wgrid = (N_NODES * 32 + 255) / 256;  // warp-per-node grids

    detect_k<<<1, 256>>>((const unsigned*)ei);

    // CSR build (once; shared by all layers)
    zeroi_k<<<(N_NODES + 255) / 256, 256>>>();
    deg_k<<<(N_EDGES + 255) / 256, 256>>>(ei);
    scan1_k<<<98, 1024>>>();
    scan2_k<<<1, 128>>>(98);
    scan3_k<<<98, 1024>>>();
    place_k<<<(N_EDGES + 255) / 256, 256>>>(ei);

    // layer 0
    build_bcat<<<256, 128>>>(Wl0, Wr0, IN_CH, KCAT0);
    build_acat<<<wgrid, 256>>>(x, IN_CH, KCAT0);
    gemm_mma<<<dim3(gx, 2), 256>>>(ac_p, KCAT0, bc_p, z_p);
    gather_combine<<<wgrid, 256>>>(z_p, b0, h_p);

    // layer 1
    build_bcat<<<256, 128>>>(Wl1, Wr1, HID, KCAT1);
    build_acat<<<wgrid, 256>>>(h_p, HID, KCAT1);
    gemm_mma<<<dim3(gx, 2), 256>>>(ac_p, KCAT1, bc_p, z_p);
    gather_combine<<<wgrid, 256>>>(z_p, b1, h_p);

    // layer 2 (transform-first: aggregate only 2 channels)
    final_gemm_k<<<N_NODES, HID>>>(h_p, Wl2, Wr2, z_p);
    gather2_k<<<(N_NODES + 255) / 256, 256>>>(z_p, b2, out);
}